// round 16
// baseline (speedup 1.0000x reference)
#include <cuda_runtime.h>
#include <cuda_bf16.h>
#include <cstdint>
#include <cstddef>

#define BB 8
#define SS 2048
#define EE 1024
#define NROWS (BB * SS)   // 16384

// ===========================================================================
// Scratch (device globals — allocation-guard-legal workspace)
// ===========================================================================
__device__ __align__(16) __nv_bfloat16 g_h_hi[(size_t)NROWS * EE];
__device__ __align__(16) __nv_bfloat16 g_h_lo[(size_t)NROWS * EE];
__device__ __align__(16) __nv_bfloat16 g_qk_hi[2 * (size_t)NROWS * EE]; // [q; k]
__device__ __align__(16) __nv_bfloat16 g_qk_lo[2 * (size_t)NROWS * EE];
__device__ __align__(16) float         g_v[(size_t)NROWS * EE];
__device__ __align__(16) __nv_bfloat16 g_vt_hi[(size_t)NROWS * EE];    // [B][EI][S]
__device__ __align__(16) __nv_bfloat16 g_vt_lo[(size_t)NROWS * EE];
__device__ __align__(16) float         g_s[(size_t)BB * SS * SS];
__device__ __align__(16) __nv_bfloat16 g_p_hi[(size_t)BB * SS * SS];
__device__ __align__(16) __nv_bfloat16 g_p_lo[(size_t)BB * SS * SS];
__device__ __align__(16) float         g_o[(size_t)NROWS * EE];
__device__ __align__(16) __nv_bfloat16 g_on_hi[(size_t)NROWS * EE];
__device__ __align__(16) __nv_bfloat16 g_on_lo[(size_t)NROWS * EE];
__device__ __align__(16) __nv_bfloat16 g_wt_hi[4 * (size_t)EE * EE];   // [WqT;WkT;WvT;WfcT]
__device__ __align__(16) __nv_bfloat16 g_wt_lo[4 * (size_t)EE * EE];

// ===========================================================================
// PTX helpers — sm_80-era, target-independent (NO tcgen05: harness compiles
// for compute_103, which rejects arch-'a' features)
// ===========================================================================
__device__ __forceinline__ uint32_t smem_u32(const void* p) {
    uint32_t a;
    asm("{ .reg .u64 t; cvta.to.shared.u64 t, %1; cvt.u32.u64 %0, t; }" : "=r"(a) : "l"(p));
    return a;
}
__device__ __forceinline__ void cp16(uint32_t dst, const void* src) {
    asm volatile("cp.async.cg.shared.global [%0], [%1], 16;" :: "r"(dst), "l"(src));
}
__device__ __forceinline__ void ldsm4(uint32_t& r0, uint32_t& r1, uint32_t& r2, uint32_t& r3,
                                      uint32_t addr) {
    asm volatile("ldmatrix.sync.aligned.m8n8.x4.shared.b16 {%0,%1,%2,%3}, [%4];"
                 : "=r"(r0), "=r"(r1), "=r"(r2), "=r"(r3) : "r"(addr));
}
__device__ __forceinline__ void mma16816(float* c, const uint32_t* a, const uint32_t* b) {
    asm volatile(
        "mma.sync.aligned.m16n8k16.row.col.f32.bf16.bf16.f32 "
        "{%0,%1,%2,%3}, {%4,%5,%6,%7}, {%8,%9}, {%0,%1,%2,%3};"
        : "+f"(c[0]), "+f"(c[1]), "+f"(c[2]), "+f"(c[3])
        : "r"(a[0]), "r"(a[1]), "r"(a[2]), "r"(a[3]), "r"(b[0]), "r"(b[1]));
}
__device__ __forceinline__ uint32_t pack_bf16(float a, float b) {
    __nv_bfloat162 h = __floats2bfloat162_rn(a, b);
    return *reinterpret_cast<uint32_t*>(&h);
}
__device__ __forceinline__ void split2(float a, float b, uint32_t& hi, uint32_t& lo) {
    __nv_bfloat16 ha = __float2bfloat16(a), hb = __float2bfloat16(b);
    float ra = a - __bfloat162float(ha), rb = b - __bfloat162float(hb);
    __nv_bfloat162 h2; h2.x = ha; h2.y = hb;
    hi = *reinterpret_cast<uint32_t*>(&h2);
    lo = pack_bf16(ra, rb);
}

// ===========================================================================
// bf16x3 split GEMM via mma.sync (HMMA): C[256x256 tile] = A[M,K] * B^T
// (A, B both K-major: A[M][K], B[N][K]; hi/lo bf16 split of each)
// 16 warps (4 m x 4 n), warp tile 64x64, BK=32, double-buffered cp.async,
// single __syncthreads per chunk. 512 threads -> 16 warps/SM (latency hiding)
// while keeping 85B smem-read/MMA fragment-reuse ratio.
// MODE 0: QKV fused over z: z<2 -> split bf16 out (+bias), z==2 -> f32 (+bias)
// MODE 1: plain f32 out (batched via z strides)
// MODE 3: f32 out = 2*(acc + bias + resid)
// ===========================================================================
#define KPAD 40                         // halves; 80B row stride (conflict-free ldsm)
#define OFF_AH 0
#define OFF_AL 20480                    // 256*40*2
#define OFF_BH 40960
#define OFF_BL 61440
#define BUF_BYTES 81920                 // 80 KB per stage
#define GEMM_SMEM (2 * BUF_BYTES)       // 160 KB

__device__ __forceinline__ void load_chunk(
    uint32_t sbuf,
    const __nv_bfloat16* __restrict__ Ah, const __nv_bfloat16* __restrict__ Al,
    const __nv_bfloat16* __restrict__ Bh, const __nv_bfloat16* __restrict__ Bl,
    long rowBase, long colBase, int K, int k0, int t)
{
    // A: 256 rows x 32 halves (64B = 4 x 16B), hi+lo
    #pragma unroll
    for (int i = 0; i < 2; i++) {
        int item = t + i * 512;            // 0..1023
        int r = item >> 2;                 // 0..255
        int sg = item & 3;                 // 16B group within 64B k-slice
        uint32_t so = (uint32_t)((r * KPAD + sg * 8) * 2);
        long ga = (rowBase + r) * (long)K + k0 + sg * 8;
        cp16(sbuf + OFF_AH + so, Ah + ga);
        cp16(sbuf + OFF_AL + so, Al + ga);
    }
    // B: 256 rows x 32 halves, hi+lo
    #pragma unroll
    for (int i = 0; i < 2; i++) {
        int item = t + i * 512;            // 0..1023
        int r = item >> 2;
        int sg = item & 3;
        uint32_t so = (uint32_t)((r * KPAD + sg * 8) * 2);
        long gb = (colBase + r) * (long)K + k0 + sg * 8;
        cp16(sbuf + OFF_BH + so, Bh + gb);
        cp16(sbuf + OFF_BL + so, Bl + gb);
    }
}

template <int MODE>
__global__ void __launch_bounds__(512, 1) hgemm3(
    const __nv_bfloat16* __restrict__ Ah_, const __nv_bfloat16* __restrict__ Al_,
    const __nv_bfloat16* __restrict__ Bh_, const __nv_bfloat16* __restrict__ Bl_,
    int K, int Ncols, long sAz, long sBz, long sCz,
    float* __restrict__ Cf_, __nv_bfloat16* __restrict__ Ch_, __nv_bfloat16* __restrict__ Cl_,
    const float* __restrict__ b0, const float* __restrict__ b1, const float* __restrict__ b2,
    const float* __restrict__ resid)
{
    extern __shared__ __align__(16) char dsm[];
    const int t = threadIdx.x;
    const int wid = t >> 5, lane = t & 31;
    const int z = blockIdx.z;
    const long rowBase = (long)blockIdx.y * 256;
    const long colBase = (long)blockIdx.x * 256;

    const __nv_bfloat16* Ah = Ah_ + (long)z * sAz;
    const __nv_bfloat16* Al = Al_ + (long)z * sAz;
    const __nv_bfloat16* Bh = Bh_ + (long)z * sBz;
    const __nv_bfloat16* Bl = Bl_ + (long)z * sBz;

    const uint32_t smem = smem_u32(dsm);
    const int mw = wid & 3;       // 4 m-warps of 64 rows
    const int nw = wid >> 2;      // 4 n-warps of 64 cols

    float acc[4][8][4];
    #pragma unroll
    for (int i = 0; i < 4; i++)
        #pragma unroll
        for (int j = 0; j < 8; j++)
            #pragma unroll
            for (int k = 0; k < 4; k++) acc[i][j][k] = 0.0f;

    const int nC = K >> 5;

    load_chunk(smem, Ah, Al, Bh, Bl, rowBase, colBase, K, 0, t);
    asm volatile("cp.async.commit_group;");

    for (int c = 0; c < nC; ++c) {
        asm volatile("cp.async.wait_group 0;" ::: "memory");
        __syncthreads();   // (a) chunk c visible to all  (b) prior compute done
        if (c + 1 < nC) {
            load_chunk(smem + ((c + 1) & 1) * BUF_BYTES, Ah, Al, Bh, Bl,
                       rowBase, colBase, K, (c + 1) << 5, t);
            asm volatile("cp.async.commit_group;");
        }

        const uint32_t sb = smem + (c & 1) * BUF_BYTES;
        #pragma unroll
        for (int ks = 0; ks < 2; ++ks) {
            uint32_t ah[4][4], al[4][4], bh[8][2], bl[8][2];
            // A fragments: rows = m, cols = k
            #pragma unroll
            for (int mt = 0; mt < 4; ++mt) {
                uint32_t row = mw * 64 + mt * 16 + (lane & 15);
                uint32_t col = ks * 16 + (lane >> 4) * 8;
                uint32_t off = (row * KPAD + col) * 2;
                ldsm4(ah[mt][0], ah[mt][1], ah[mt][2], ah[mt][3], sb + OFF_AH + off);
                ldsm4(al[mt][0], al[mt][1], al[mt][2], al[mt][3], sb + OFF_AL + off);
            }
            // B fragments: rows = n, cols = k ([n][k] == col-major B)
            #pragma unroll
            for (int np = 0; np < 4; ++np) {
                uint32_t row = nw * 64 + np * 16 + (lane >> 4) * 8 + (lane & 7);
                uint32_t col = ks * 16 + ((lane >> 3) & 1) * 8;
                uint32_t off = (row * KPAD + col) * 2;
                uint32_t r0, r1, r2, r3;
                ldsm4(r0, r1, r2, r3, sb + OFF_BH + off);
                bh[2 * np][0] = r0; bh[2 * np][1] = r1;
                bh[2 * np + 1][0] = r2; bh[2 * np + 1][1] = r3;
                ldsm4(r0, r1, r2, r3, sb + OFF_BL + off);
                bl[2 * np][0] = r0; bl[2 * np][1] = r1;
                bl[2 * np + 1][0] = r2; bl[2 * np + 1][1] = r3;
            }
            // 3-term split product; term-major spaces same-acc RAW by 32 mmas
            #pragma unroll
            for (int mt = 0; mt < 4; ++mt)
                #pragma unroll
                for (int nt = 0; nt < 8; ++nt) mma16816(acc[mt][nt], ah[mt], bh[nt]);
            #pragma unroll
            for (int mt = 0; mt < 4; ++mt)
                #pragma unroll
                for (int nt = 0; nt < 8; ++nt) mma16816(acc[mt][nt], ah[mt], bl[nt]);
            #pragma unroll
            for (int mt = 0; mt < 4; ++mt)
                #pragma unroll
                for (int nt = 0; nt < 8; ++nt) mma16816(acc[mt][nt], al[mt], bh[nt]);
        }
    }

    // ---- epilogue: direct register->gmem stores (quad-contiguous) ----
    const int g = lane >> 2, tg = lane & 3;
    float be[8][2];
    if (MODE == 0 || MODE == 3) {
        const float* bb = (MODE == 3) ? b0 : ((z == 0) ? b0 : ((z == 1) ? b1 : b2));
        #pragma unroll
        for (int nt = 0; nt < 8; ++nt) {
            long col = colBase + nw * 64 + nt * 8 + tg * 2;
            be[nt][0] = bb[col]; be[nt][1] = bb[col + 1];
        }
    }

    #pragma unroll
    for (int mt = 0; mt < 4; ++mt) {
        long r0 = rowBase + mw * 64 + mt * 16 + g;
        long r1 = r0 + 8;
        #pragma unroll
        for (int nt = 0; nt < 8; ++nt) {
            long col = colBase + nw * 64 + nt * 8 + tg * 2;
            float v00 = acc[mt][nt][0], v01 = acc[mt][nt][1];
            float v10 = acc[mt][nt][2], v11 = acc[mt][nt][3];
            if (MODE == 0) {
                v00 += be[nt][0]; v01 += be[nt][1];
                v10 += be[nt][0]; v11 += be[nt][1];
                if (z < 2) {
                    long o0 = (long)z * ((long)NROWS * EE) + r0 * (long)Ncols + col;
                    long o1 = (long)z * ((long)NROWS * EE) + r1 * (long)Ncols + col;
                    uint32_t h0, l0, h1, l1;
                    split2(v00, v01, h0, l0);
                    split2(v10, v11, h1, l1);
                    *reinterpret_cast<uint32_t*>(Ch_ + o0) = h0;
                    *reinterpret_cast<uint32_t*>(Cl_ + o0) = l0;
                    *reinterpret_cast<uint32_t*>(Ch_ + o1) = h1;
                    *reinterpret_cast<uint32_t*>(Cl_ + o1) = l1;
                } else {
                    *reinterpret_cast<float2*>(Cf_ + r0 * (long)Ncols + col) = make_float2(v00, v01);
                    *reinterpret_cast<float2*>(Cf_ + r1 * (long)Ncols + col) = make_float2(v10, v11);
                }
            } else if (MODE == 1) {
                float* Cz = Cf_ + (long)z * sCz;
                *reinterpret_cast<float2*>(Cz + r0 * (long)Ncols + col) = make_float2(v00, v01);
                *reinterpret_cast<float2*>(Cz + r1 * (long)Ncols + col) = make_float2(v10, v11);
            } else { // MODE 3
                long o0 = r0 * (long)Ncols + col;
                long o1 = r1 * (long)Ncols + col;
                float2 x0 = *reinterpret_cast<const float2*>(resid + o0);
                float2 x1 = *reinterpret_cast<const float2*>(resid + o1);
                *reinterpret_cast<float2*>(Cf_ + o0) =
                    make_float2(2.0f * (v00 + be[nt][0] + x0.x), 2.0f * (v01 + be[nt][1] + x0.y));
                *reinterpret_cast<float2*>(Cf_ + o1) =
                    make_float2(2.0f * (v10 + be[nt][0] + x1.x), 2.0f * (v11 + be[nt][1] + x1.y));
            }
        }
    }
}

// ===========================================================================
// Block reductions (256 threads)
// ===========================================================================
__device__ __forceinline__ float blockReduceSum(float v, float* red) {
    #pragma unroll
    for (int o = 16; o > 0; o >>= 1) v += __shfl_xor_sync(0xffffffffu, v, o);
    int t = threadIdx.x;
    if ((t & 31) == 0) red[t >> 5] = v;
    __syncthreads();
    if (t < 32) {
        float r = (t < 8) ? red[t] : 0.0f;
        #pragma unroll
        for (int o = 4; o > 0; o >>= 1) r += __shfl_xor_sync(0xffffffffu, r, o);
        if (t == 0) red[0] = r;
    }
    __syncthreads();
    float out = red[0];
    __syncthreads();
    return out;
}
__device__ __forceinline__ float blockReduceMax(float v, float* red) {
    #pragma unroll
    for (int o = 16; o > 0; o >>= 1) v = fmaxf(v, __shfl_xor_sync(0xffffffffu, v, o));
    int t = threadIdx.x;
    if ((t & 31) == 0) red[t >> 5] = v;
    __syncthreads();
    if (t < 32) {
        float r = (t < 8) ? red[t] : -3.0e38f;
        #pragma unroll
        for (int o = 4; o > 0; o >>= 1) r = fmaxf(r, __shfl_xor_sync(0xffffffffu, r, o));
        if (t == 0) red[0] = r;
    }
    __syncthreads();
    float out = red[0];
    __syncthreads();
    return out;
}

// ===========================================================================
// LayerNorm(1024) -> bf16 hi/lo split
// ===========================================================================
__global__ __launch_bounds__(256) void ln_split(const float* __restrict__ in,
                                                const float* __restrict__ gam,
                                                const float* __restrict__ bet,
                                                __nv_bfloat16* __restrict__ oh,
                                                __nv_bfloat16* __restrict__ ol) {
    __shared__ float red[8];
    const long row = blockIdx.x;
    const float* x = in + row * (long)EE;
    const int t = threadIdx.x;
    float4 xv = *reinterpret_cast<const float4*>(&x[t * 4]);

    float s = blockReduceSum(xv.x + xv.y + xv.z + xv.w, red);
    float mu = s * (1.0f / 1024.0f);
    float d0 = xv.x - mu, d1 = xv.y - mu, d2 = xv.z - mu, d3 = xv.w - mu;
    float ss = blockReduceSum(d0 * d0 + d1 * d1 + d2 * d2 + d3 * d3, red);
    float r = rsqrtf(ss * (1.0f / 1024.0f) + 1e-5f);

    float4 g4 = *reinterpret_cast<const float4*>(&gam[t * 4]);
    float4 b4 = *reinterpret_cast<const float4*>(&bet[t * 4]);
    float ov[4];
    ov[0] = d0 * r * g4.x + b4.x; ov[1] = d1 * r * g4.y + b4.y;
    ov[2] = d2 * r * g4.z + b4.z; ov[3] = d3 * r * g4.w + b4.w;

    uint32_t hw[2], lw[2];
    split2(ov[0], ov[1], hw[0], lw[0]);
    split2(ov[2], ov[3], hw[1], lw[1]);
    long base = row * (long)EE + t * 4;
    *reinterpret_cast<uint2*>(&oh[base]) = make_uint2(hw[0], hw[1]);
    *reinterpret_cast<uint2*>(&ol[base]) = make_uint2(lw[0], lw[1]);
}

// ===========================================================================
// Softmax(2048) -> bf16 hi/lo split
// ===========================================================================
__global__ __launch_bounds__(256) void softmax_split(const float* __restrict__ sc,
                                                     __nv_bfloat16* __restrict__ ph,
                                                     __nv_bfloat16* __restrict__ pl) {
    __shared__ float red[8];
    const long row = blockIdx.x;
    const float* p = sc + row * (long)SS;
    const int t = threadIdx.x;
    float4 a = *reinterpret_cast<const float4*>(&p[t * 8]);
    float4 b = *reinterpret_cast<const float4*>(&p[t * 8 + 4]);

    float m = fmaxf(fmaxf(fmaxf(a.x, a.y), fmaxf(a.z, a.w)),
                    fmaxf(fmaxf(b.x, b.y), fmaxf(b.z, b.w)));
    m = blockReduceMax(m, red);

    float e[8];
    e[0] = __expf(a.x - m); e[1] = __expf(a.y - m); e[2] = __expf(a.z - m); e[3] = __expf(a.w - m);
    e[4] = __expf(b.x - m); e[5] = __expf(b.y - m); e[6] = __expf(b.z - m); e[7] = __expf(b.w - m);

    float s = (e[0] + e[1] + e[2] + e[3]) + (e[4] + e[5] + e[6] + e[7]);
    s = blockReduceSum(s, red);
    float inv = 1.0f / s;

    uint32_t hw[4], lw[4];
    #pragma unroll
    for (int i = 0; i < 4; i++)
        split2(e[2 * i] * inv, e[2 * i + 1] * inv, hw[i], lw[i]);
    long base = row * (long)SS + t * 8;
    *reinterpret_cast<uint4*>(&ph[base]) = make_uint4(hw[0], hw[1], hw[2], hw[3]);
    *reinterpret_cast<uint4*>(&pl[base]) = make_uint4(lw[0], lw[1], lw[2], lw[3]);
}

// ===========================================================================
// Transpose + split: in[R][C] (f32) -> out[C][R] (bf16 hi/lo), batched via z
// ===========================================================================
__global__ void transpose_split(const float* __restrict__ in,
                                __nv_bfloat16* __restrict__ oh,
                                __nv_bfloat16* __restrict__ ol,
                                int R, int C, long siz, long soz) {
    __shared__ float tl[32][33];
    const float* ip = in + (long)blockIdx.z * siz;
    const int x = blockIdx.x * 32 + threadIdx.x;
    const int y0 = blockIdx.y * 32;
    #pragma unroll
    for (int j = 0; j < 32; j += 8)
        tl[threadIdx.y + j][threadIdx.x] = ip[(long)(y0 + threadIdx.y + j) * C + x];
    __syncthreads();
    #pragma unroll
    for (int j = 0; j < 32; j += 8) {
        float v = tl[threadIdx.x][threadIdx.y + j];
        __nv_bfloat16 hi = __float2bfloat16(v);
        __nv_bfloat16 lo = __float2bfloat16(v - __bfloat162float(hi));
        long o = (long)blockIdx.z * soz +
                 (long)(blockIdx.x * 32 + threadIdx.y + j) * R + y0 + threadIdx.x;
        oh[o] = hi; ol[o] = lo;
    }
}

// ===========================================================================
// Launch sequence
// ===========================================================================
extern "C" void kernel_launch(void* const* d_in, const int* in_sizes, int n_in,
                              void* d_out, int out_size) {
    const float* x   = (const float*)d_in[0];
    const float* Wq  = (const float*)d_in[1];
    const float* bq  = (const float*)d_in[2];
    const float* Wk  = (const float*)d_in[3];
    const float* bk  = (const float*)d_in[4];
    const float* Wv  = (const float*)d_in[5];
    const float* bv  = (const float*)d_in[6];
    const float* Wfc = (const float*)d_in[7];
    const float* bfc = (const float*)d_in[8];
    const float* g1  = (const float*)d_in[9];
    const float* b1  = (const float*)d_in[10];
    const float* g2  = (const float*)d_in[11];
    const float* b2  = (const float*)d_in[12];
    float* out = (float*)d_out;

    __nv_bfloat16 *hHi, *hLo, *qkHi, *qkLo, *vtHi, *vtLo, *pHi, *pLo, *onHi, *onLo, *wtHi, *wtLo;
    float *vF, *sF, *oF;
    cudaGetSymbolAddress((void**)&hHi, g_h_hi);   cudaGetSymbolAddress((void**)&hLo, g_h_lo);
    cudaGetSymbolAddress((void**)&qkHi, g_qk_hi); cudaGetSymbolAddress((void**)&qkLo, g_qk_lo);
    cudaGetSymbolAddress((void**)&vF, g_v);
    cudaGetSymbolAddress((void**)&vtHi, g_vt_hi); cudaGetSymbolAddress((void**)&vtLo, g_vt_lo);
    cudaGetSymbolAddress((void**)&sF, g_s);
    cudaGetSymbolAddress((void**)&pHi, g_p_hi);   cudaGetSymbolAddress((void**)&pLo, g_p_lo);
    cudaGetSymbolAddress((void**)&oF, g_o);
    cudaGetSymbolAddress((void**)&onHi, g_on_hi); cudaGetSymbolAddress((void**)&onLo, g_on_lo);
    cudaGetSymbolAddress((void**)&wtHi, g_wt_hi); cudaGetSymbolAddress((void**)&wtLo, g_wt_lo);

    cudaFuncSetAttribute(hgemm3<0>, cudaFuncAttributeMaxDynamicSharedMemorySize, GEMM_SMEM);
    cudaFuncSetAttribute(hgemm3<1>, cudaFuncAttributeMaxDynamicSharedMemorySize, GEMM_SMEM);
    cudaFuncSetAttribute(hgemm3<3>, cudaFuncAttributeMaxDynamicSharedMemorySize, GEMM_SMEM);

    const long EE2 = (long)EE * EE;
    dim3 tb(32, 8);

    // 0) weight transposes + splits: wt[i][n][k] = W_i[k][n]
    transpose_split<<<dim3(32, 32, 1), tb>>>(Wq,  wtHi + 0 * EE2, wtLo + 0 * EE2, EE, EE, 0, 0);
    transpose_split<<<dim3(32, 32, 1), tb>>>(Wk,  wtHi + 1 * EE2, wtLo + 1 * EE2, EE, EE, 0, 0);
    transpose_split<<<dim3(32, 32, 1), tb>>>(Wv,  wtHi + 2 * EE2, wtLo + 2 * EE2, EE, EE, 0, 0);
    transpose_split<<<dim3(32, 32, 1), tb>>>(Wfc, wtHi + 3 * EE2, wtLo + 3 * EE2, EE, EE, 0, 0);

    // 1) h = LN(x) -> splits
    ln_split<<<NROWS, 256>>>(x, g1, b1, hHi, hLo);

    // 2) fused QKV: z in {0:q split, 1:k split, 2:v f32}
    hgemm3<0><<<dim3(EE / 256, NROWS / 256, 3), 512, GEMM_SMEM>>>(
        hHi, hLo, wtHi, wtLo, EE, EE, 0, EE2, 0,
        vF, qkHi, qkLo, bq, bk, bv, nullptr);

    // 3) v transpose+split: [B][S][EI] -> [B][EI][S]
    transpose_split<<<dim3(EE / 32, SS / 32, BB), tb>>>(
        vF, vtHi, vtLo, SS, EE, (long)SS * EE, (long)EE * SS);

    // 4) scores = q @ k^T per batch (f32 out)
    hgemm3<1><<<dim3(SS / 256, SS / 256, BB), 512, GEMM_SMEM>>>(
        qkHi, qkLo, qkHi + (long)NROWS * EE, qkLo + (long)NROWS * EE,
        EE, SS, (long)SS * EE, (long)SS * EE, (long)SS * SS,
        sF, nullptr, nullptr, nullptr, nullptr, nullptr, nullptr);

    // 5) softmax + split
    softmax_split<<<BB * SS, 256>>>(sF, pHi, pLo);

    // 6) o = attn @ v per batch (B = vt[EI][S])
    hgemm3<1><<<dim3(EE / 256, SS / 256, BB), 512, GEMM_SMEM>>>(
        pHi, pLo, vtHi, vtLo,
        SS, EE, (long)SS * SS, (long)EE * SS, (long)SS * EE,
        oF, nullptr, nullptr, nullptr, nullptr, nullptr, nullptr);

    // 7) LN2 -> splits
    ln_split<<<NROWS, 256>>>(oF, g2, b2, onHi, onLo);

    // 8) out = 2*(oln @ Wfc + bfc + x)
    hgemm3<3><<<dim3(EE / 256, NROWS / 256, 1), 512, GEMM_SMEM>>>(
        onHi, onLo, wtHi + 3 * EE2, wtLo + 3 * EE2,
        EE, EE, 0, 0, 0,
        out, nullptr, nullptr, bfc, nullptr, nullptr, x);
}

// round 17
// speedup vs baseline: 2.1836x; 2.1836x over previous
#include <cuda_runtime.h>
#include <cuda_bf16.h>
#include <cstdint>
#include <cstddef>

#define BB 8
#define SS 2048
#define EE 1024
#define NROWS (BB * SS)   // 16384

// ===========================================================================
// Scratch (device globals — allocation-guard-legal workspace)
// ===========================================================================
__device__ __align__(16) __nv_bfloat16 g_h_hi[(size_t)NROWS * EE];
__device__ __align__(16) __nv_bfloat16 g_h_lo[(size_t)NROWS * EE];
__device__ __align__(16) __nv_bfloat16 g_qk_hi[2 * (size_t)NROWS * EE]; // [q; k]
__device__ __align__(16) __nv_bfloat16 g_qk_lo[2 * (size_t)NROWS * EE];
__device__ __align__(16) float         g_v[(size_t)NROWS * EE];
__device__ __align__(16) __nv_bfloat16 g_vt_hi[(size_t)NROWS * EE];    // [B][EI][S]
__device__ __align__(16) __nv_bfloat16 g_vt_lo[(size_t)NROWS * EE];
__device__ __align__(16) float         g_s[(size_t)BB * SS * SS];
__device__ __align__(16) __nv_bfloat16 g_p_hi[(size_t)BB * SS * SS];
__device__ __align__(16) __nv_bfloat16 g_p_lo[(size_t)BB * SS * SS];
__device__ __align__(16) float         g_o[(size_t)NROWS * EE];
__device__ __align__(16) __nv_bfloat16 g_on_hi[(size_t)NROWS * EE];
__device__ __align__(16) __nv_bfloat16 g_on_lo[(size_t)NROWS * EE];
__device__ __align__(16) __nv_bfloat16 g_wt_hi[4 * (size_t)EE * EE];   // [WqT;WkT;WvT;WfcT]
__device__ __align__(16) __nv_bfloat16 g_wt_lo[4 * (size_t)EE * EE];

// ===========================================================================
// PTX helpers — sm_80-era, target-independent (NO tcgen05: harness compiles
// for compute_103, which rejects arch-'a' features)
// ===========================================================================
__device__ __forceinline__ uint32_t smem_u32(const void* p) {
    uint32_t a;
    asm("{ .reg .u64 t; cvta.to.shared.u64 t, %1; cvt.u32.u64 %0, t; }" : "=r"(a) : "l"(p));
    return a;
}
__device__ __forceinline__ void cp16(uint32_t dst, const void* src) {
    asm volatile("cp.async.cg.shared.global [%0], [%1], 16;" :: "r"(dst), "l"(src));
}
__device__ __forceinline__ void ldsm4(uint32_t& r0, uint32_t& r1, uint32_t& r2, uint32_t& r3,
                                      uint32_t addr) {
    asm volatile("ldmatrix.sync.aligned.m8n8.x4.shared.b16 {%0,%1,%2,%3}, [%4];"
                 : "=r"(r0), "=r"(r1), "=r"(r2), "=r"(r3) : "r"(addr));
}
__device__ __forceinline__ void mma16816(float* c, const uint32_t* a, const uint32_t* b) {
    asm volatile(
        "mma.sync.aligned.m16n8k16.row.col.f32.bf16.bf16.f32 "
        "{%0,%1,%2,%3}, {%4,%5,%6,%7}, {%8,%9}, {%0,%1,%2,%3};"
        : "+f"(c[0]), "+f"(c[1]), "+f"(c[2]), "+f"(c[3])
        : "r"(a[0]), "r"(a[1]), "r"(a[2]), "r"(a[3]), "r"(b[0]), "r"(b[1]));
}
__device__ __forceinline__ uint32_t pack_bf16(float a, float b) {
    __nv_bfloat162 h = __floats2bfloat162_rn(a, b);
    return *reinterpret_cast<uint32_t*>(&h);
}
__device__ __forceinline__ void split2(float a, float b, uint32_t& hi, uint32_t& lo) {
    __nv_bfloat16 ha = __float2bfloat16(a), hb = __float2bfloat16(b);
    float ra = a - __bfloat162float(ha), rb = b - __bfloat162float(hb);
    __nv_bfloat162 h2; h2.x = ha; h2.y = hb;
    hi = *reinterpret_cast<uint32_t*>(&h2);
    lo = pack_bf16(ra, rb);
}

// ===========================================================================
// bf16x3 split GEMM via mma.sync (HMMA): C[128x128 tile] = A[M,K] * B^T
// (A, B both K-major: A[M][K], B[N][K]; hi/lo bf16 split of each)
// 8 warps (4 m x 2 n), warp tile 32x64, BK=32.
// Packed smem rows: [hi(32h) | lo(32h) | pad(8h)] stride 72 halves (144B) —
// conflict-free for cp.async 16B stores and ldmatrix phases; stage = 36KB,
// double-buffered = 72KB -> 3 CTAs/SM (24 warps). One __syncthreads/chunk.
// MODE 0: QKV fused over z: z<2 -> split bf16 out (+bias), z==2 -> f32 (+bias)
// MODE 1: plain f32 out (batched via z strides)
// MODE 3: f32 out = 2*(acc + bias + resid)
// ===========================================================================
#define RSTRIDE 144                      // bytes per packed row (72 halves)
#define SM_B_OFF (128 * RSTRIDE)         // 18432
#define BUF_BYTES (2 * 128 * RSTRIDE)    // 36864 per stage
#define GEMM_SMEM (2 * BUF_BYTES)        // 73728

__device__ __forceinline__ void load_chunk(
    uint32_t sbuf,
    const __nv_bfloat16* __restrict__ Ah, const __nv_bfloat16* __restrict__ Al,
    const __nv_bfloat16* __restrict__ Bh, const __nv_bfloat16* __restrict__ Bl,
    long rowBase, long colBase, int K, int k0, int t)
{
    // A: 128 rows x 8 groups of 16B (g<4 -> hi sg=g, g>=4 -> lo sg=g-4)
    #pragma unroll
    for (int i = 0; i < 4; i++) {
        int item = t + i * 256;            // 0..1023
        int r = item >> 3;                 // 0..127
        int g = item & 7;
        int sg = g & 3;
        const __nv_bfloat16* src = (g < 4) ? Ah : Al;
        uint32_t so = (uint32_t)(r * RSTRIDE + g * 16);
        cp16(sbuf + so, src + (rowBase + r) * (long)K + k0 + sg * 8);
    }
    // B: 128 rows x 8 groups
    #pragma unroll
    for (int i = 0; i < 4; i++) {
        int item = t + i * 256;
        int r = item >> 3;
        int g = item & 7;
        int sg = g & 3;
        const __nv_bfloat16* src = (g < 4) ? Bh : Bl;
        uint32_t so = (uint32_t)(SM_B_OFF + r * RSTRIDE + g * 16);
        cp16(sbuf + so, src + (colBase + r) * (long)K + k0 + sg * 8);
    }
}

template <int MODE>
__global__ void __launch_bounds__(256) hgemm3(
    const __nv_bfloat16* __restrict__ Ah_, const __nv_bfloat16* __restrict__ Al_,
    const __nv_bfloat16* __restrict__ Bh_, const __nv_bfloat16* __restrict__ Bl_,
    int K, int Ncols, long sAz, long sBz, long sCz,
    float* __restrict__ Cf_, __nv_bfloat16* __restrict__ Ch_, __nv_bfloat16* __restrict__ Cl_,
    const float* __restrict__ b0, const float* __restrict__ b1, const float* __restrict__ b2,
    const float* __restrict__ resid)
{
    extern __shared__ __align__(16) char dsm[];
    const int t = threadIdx.x;
    const int wid = t >> 5, lane = t & 31;
    const int z = blockIdx.z;
    const long rowBase = (long)blockIdx.y * 128;
    const long colBase = (long)blockIdx.x * 128;

    const __nv_bfloat16* Ah = Ah_ + (long)z * sAz;
    const __nv_bfloat16* Al = Al_ + (long)z * sAz;
    const __nv_bfloat16* Bh = Bh_ + (long)z * sBz;
    const __nv_bfloat16* Bl = Bl_ + (long)z * sBz;

    const uint32_t smem = smem_u32(dsm);
    const int mw = wid & 3;       // 4 m-warps of 32 rows
    const int nw = wid >> 2;      // 2 n-warps of 64 cols

    float acc[2][8][4];
    #pragma unroll
    for (int i = 0; i < 2; i++)
        #pragma unroll
        for (int j = 0; j < 8; j++)
            #pragma unroll
            for (int k = 0; k < 4; k++) acc[i][j][k] = 0.0f;

    const int nC = K >> 5;

    load_chunk(smem, Ah, Al, Bh, Bl, rowBase, colBase, K, 0, t);
    asm volatile("cp.async.commit_group;");

    for (int c = 0; c < nC; ++c) {
        asm volatile("cp.async.wait_group 0;" ::: "memory");
        __syncthreads();   // (a) chunk c visible  (b) prior compute on other buf done
        if (c + 1 < nC) {
            load_chunk(smem + ((c + 1) & 1) * BUF_BYTES, Ah, Al, Bh, Bl,
                       rowBase, colBase, K, (c + 1) << 5, t);
            asm volatile("cp.async.commit_group;");
        }

        const uint32_t sb = smem + (c & 1) * BUF_BYTES;
        #pragma unroll
        for (int ks = 0; ks < 2; ++ks) {
            uint32_t ah[2][4], al[2][4], bh[8][2], bl[8][2];
            // A fragments: rows = m, cols = k; hi at +0, lo at +64B
            #pragma unroll
            for (int mt = 0; mt < 2; ++mt) {
                uint32_t row = mw * 32 + mt * 16 + (lane & 15);
                uint32_t col = ks * 16 + (lane >> 4) * 8;       // halves (hi region)
                uint32_t off = row * RSTRIDE + col * 2;
                ldsm4(ah[mt][0], ah[mt][1], ah[mt][2], ah[mt][3], sb + off);
                ldsm4(al[mt][0], al[mt][1], al[mt][2], al[mt][3], sb + off + 64);
            }
            // B fragments: rows = n, cols = k ([n][k] == col-major B)
            #pragma unroll
            for (int np = 0; np < 4; ++np) {
                uint32_t row = nw * 64 + np * 16 + (lane >> 4) * 8 + (lane & 7);
                uint32_t col = ks * 16 + ((lane >> 3) & 1) * 8;
                uint32_t off = SM_B_OFF + row * RSTRIDE + col * 2;
                uint32_t r0, r1, r2, r3;
                ldsm4(r0, r1, r2, r3, sb + off);
                bh[2 * np][0] = r0; bh[2 * np][1] = r1;
                bh[2 * np + 1][0] = r2; bh[2 * np + 1][1] = r3;
                ldsm4(r0, r1, r2, r3, sb + off + 64);
                bl[2 * np][0] = r0; bl[2 * np][1] = r1;
                bl[2 * np + 1][0] = r2; bl[2 * np + 1][1] = r3;
            }
            // 3-term split product; term-major spaces same-acc RAW by 16 mmas
            #pragma unroll
            for (int mt = 0; mt < 2; ++mt)
                #pragma unroll
                for (int nt = 0; nt < 8; ++nt) mma16816(acc[mt][nt], ah[mt], bh[nt]);
            #pragma unroll
            for (int mt = 0; mt < 2; ++mt)
                #pragma unroll
                for (int nt = 0; nt < 8; ++nt) mma16816(acc[mt][nt], ah[mt], bl[nt]);
            #pragma unroll
            for (int mt = 0; mt < 2; ++mt)
                #pragma unroll
                for (int nt = 0; nt < 8; ++nt) mma16816(acc[mt][nt], al[mt], bh[nt]);
        }
    }

    // ---- epilogue: direct register->gmem stores (quad-contiguous) ----
    const int g = lane >> 2, tg = lane & 3;
    float be[8][2];
    if (MODE == 0 || MODE == 3) {
        const float* bb = (MODE == 3) ? b0 : ((z == 0) ? b0 : ((z == 1) ? b1 : b2));
        #pragma unroll
        for (int nt = 0; nt < 8; ++nt) {
            long col = colBase + nw * 64 + nt * 8 + tg * 2;
            be[nt][0] = bb[col]; be[nt][1] = bb[col + 1];
        }
    }

    #pragma unroll
    for (int mt = 0; mt < 2; ++mt) {
        long r0 = rowBase + mw * 32 + mt * 16 + g;
        long r1 = r0 + 8;
        #pragma unroll
        for (int nt = 0; nt < 8; ++nt) {
            long col = colBase + nw * 64 + nt * 8 + tg * 2;
            float v00 = acc[mt][nt][0], v01 = acc[mt][nt][1];
            float v10 = acc[mt][nt][2], v11 = acc[mt][nt][3];
            if (MODE == 0) {
                v00 += be[nt][0]; v01 += be[nt][1];
                v10 += be[nt][0]; v11 += be[nt][1];
                if (z < 2) {
                    long o0 = (long)z * ((long)NROWS * EE) + r0 * (long)Ncols + col;
                    long o1 = (long)z * ((long)NROWS * EE) + r1 * (long)Ncols + col;
                    uint32_t h0, l0, h1, l1;
                    split2(v00, v01, h0, l0);
                    split2(v10, v11, h1, l1);
                    *reinterpret_cast<uint32_t*>(Ch_ + o0) = h0;
                    *reinterpret_cast<uint32_t*>(Cl_ + o0) = l0;
                    *reinterpret_cast<uint32_t*>(Ch_ + o1) = h1;
                    *reinterpret_cast<uint32_t*>(Cl_ + o1) = l1;
                } else {
                    *reinterpret_cast<float2*>(Cf_ + r0 * (long)Ncols + col) = make_float2(v00, v01);
                    *reinterpret_cast<float2*>(Cf_ + r1 * (long)Ncols + col) = make_float2(v10, v11);
                }
            } else if (MODE == 1) {
                float* Cz = Cf_ + (long)z * sCz;
                *reinterpret_cast<float2*>(Cz + r0 * (long)Ncols + col) = make_float2(v00, v01);
                *reinterpret_cast<float2*>(Cz + r1 * (long)Ncols + col) = make_float2(v10, v11);
            } else { // MODE 3
                long o0 = r0 * (long)Ncols + col;
                long o1 = r1 * (long)Ncols + col;
                float2 x0 = *reinterpret_cast<const float2*>(resid + o0);
                float2 x1 = *reinterpret_cast<const float2*>(resid + o1);
                *reinterpret_cast<float2*>(Cf_ + o0) =
                    make_float2(2.0f * (v00 + be[nt][0] + x0.x), 2.0f * (v01 + be[nt][1] + x0.y));
                *reinterpret_cast<float2*>(Cf_ + o1) =
                    make_float2(2.0f * (v10 + be[nt][0] + x1.x), 2.0f * (v11 + be[nt][1] + x1.y));
            }
        }
    }
}

// ===========================================================================
// Block reductions (256 threads)
// ===========================================================================
__device__ __forceinline__ float blockReduceSum(float v, float* red) {
    #pragma unroll
    for (int o = 16; o > 0; o >>= 1) v += __shfl_xor_sync(0xffffffffu, v, o);
    int t = threadIdx.x;
    if ((t & 31) == 0) red[t >> 5] = v;
    __syncthreads();
    if (t < 32) {
        float r = (t < 8) ? red[t] : 0.0f;
        #pragma unroll
        for (int o = 4; o > 0; o >>= 1) r += __shfl_xor_sync(0xffffffffu, r, o);
        if (t == 0) red[0] = r;
    }
    __syncthreads();
    float out = red[0];
    __syncthreads();
    return out;
}
__device__ __forceinline__ float blockReduceMax(float v, float* red) {
    #pragma unroll
    for (int o = 16; o > 0; o >>= 1) v = fmaxf(v, __shfl_xor_sync(0xffffffffu, v, o));
    int t = threadIdx.x;
    if ((t & 31) == 0) red[t >> 5] = v;
    __syncthreads();
    if (t < 32) {
        float r = (t < 8) ? red[t] : -3.0e38f;
        #pragma unroll
        for (int o = 4; o > 0; o >>= 1) r = fmaxf(r, __shfl_xor_sync(0xffffffffu, r, o));
        if (t == 0) red[0] = r;
    }
    __syncthreads();
    float out = red[0];
    __syncthreads();
    return out;
}

// ===========================================================================
// LayerNorm(1024) -> bf16 hi/lo split
// ===========================================================================
__global__ __launch_bounds__(256) void ln_split(const float* __restrict__ in,
                                                const float* __restrict__ gam,
                                                const float* __restrict__ bet,
                                                __nv_bfloat16* __restrict__ oh,
                                                __nv_bfloat16* __restrict__ ol) {
    __shared__ float red[8];
    const long row = blockIdx.x;
    const float* x = in + row * (long)EE;
    const int t = threadIdx.x;
    float4 xv = *reinterpret_cast<const float4*>(&x[t * 4]);

    float s = blockReduceSum(xv.x + xv.y + xv.z + xv.w, red);
    float mu = s * (1.0f / 1024.0f);
    float d0 = xv.x - mu, d1 = xv.y - mu, d2 = xv.z - mu, d3 = xv.w - mu;
    float ss = blockReduceSum(d0 * d0 + d1 * d1 + d2 * d2 + d3 * d3, red);
    float r = rsqrtf(ss * (1.0f / 1024.0f) + 1e-5f);

    float4 g4 = *reinterpret_cast<const float4*>(&gam[t * 4]);
    float4 b4 = *reinterpret_cast<const float4*>(&bet[t * 4]);
    float ov[4];
    ov[0] = d0 * r * g4.x + b4.x; ov[1] = d1 * r * g4.y + b4.y;
    ov[2] = d2 * r * g4.z + b4.z; ov[3] = d3 * r * g4.w + b4.w;

    uint32_t hw[2], lw[2];
    split2(ov[0], ov[1], hw[0], lw[0]);
    split2(ov[2], ov[3], hw[1], lw[1]);
    long base = row * (long)EE + t * 4;
    *reinterpret_cast<uint2*>(&oh[base]) = make_uint2(hw[0], hw[1]);
    *reinterpret_cast<uint2*>(&ol[base]) = make_uint2(lw[0], lw[1]);
}

// ===========================================================================
// Softmax(2048) -> bf16 hi/lo split
// ===========================================================================
__global__ __launch_bounds__(256) void softmax_split(const float* __restrict__ sc,
                                                     __nv_bfloat16* __restrict__ ph,
                                                     __nv_bfloat16* __restrict__ pl) {
    __shared__ float red[8];
    const long row = blockIdx.x;
    const float* p = sc + row * (long)SS;
    const int t = threadIdx.x;
    float4 a = *reinterpret_cast<const float4*>(&p[t * 8]);
    float4 b = *reinterpret_cast<const float4*>(&p[t * 8 + 4]);

    float m = fmaxf(fmaxf(fmaxf(a.x, a.y), fmaxf(a.z, a.w)),
                    fmaxf(fmaxf(b.x, b.y), fmaxf(b.z, b.w)));
    m = blockReduceMax(m, red);

    float e[8];
    e[0] = __expf(a.x - m); e[1] = __expf(a.y - m); e[2] = __expf(a.z - m); e[3] = __expf(a.w - m);
    e[4] = __expf(b.x - m); e[5] = __expf(b.y - m); e[6] = __expf(b.z - m); e[7] = __expf(b.w - m);

    float s = (e[0] + e[1] + e[2] + e[3]) + (e[4] + e[5] + e[6] + e[7]);
    s = blockReduceSum(s, red);
    float inv = 1.0f / s;

    uint32_t hw[4], lw[4];
    #pragma unroll
    for (int i = 0; i < 4; i++)
        split2(e[2 * i] * inv, e[2 * i + 1] * inv, hw[i], lw[i]);
    long base = row * (long)SS + t * 8;
    *reinterpret_cast<uint4*>(&ph[base]) = make_uint4(hw[0], hw[1], hw[2], hw[3]);
    *reinterpret_cast<uint4*>(&pl[base]) = make_uint4(lw[0], lw[1], lw[2], lw[3]);
}

// ===========================================================================
// Transpose + split: in[R][C] (f32) -> out[C][R] (bf16 hi/lo), batched via z
// ===========================================================================
__global__ void transpose_split(const float* __restrict__ in,
                                __nv_bfloat16* __restrict__ oh,
                                __nv_bfloat16* __restrict__ ol,
                                int R, int C, long siz, long soz) {
    __shared__ float tl[32][33];
    const float* ip = in + (long)blockIdx.z * siz;
    const int x = blockIdx.x * 32 + threadIdx.x;
    const int y0 = blockIdx.y * 32;
    #pragma unroll
    for (int j = 0; j < 32; j += 8)
        tl[threadIdx.y + j][threadIdx.x] = ip[(long)(y0 + threadIdx.y + j) * C + x];
    __syncthreads();
    #pragma unroll
    for (int j = 0; j < 32; j += 8) {
        float v = tl[threadIdx.x][threadIdx.y + j];
        __nv_bfloat16 hi = __float2bfloat16(v);
        __nv_bfloat16 lo = __float2bfloat16(v - __bfloat162float(hi));
        long o = (long)blockIdx.z * soz +
                 (long)(blockIdx.x * 32 + threadIdx.y + j) * R + y0 + threadIdx.x;
        oh[o] = hi; ol[o] = lo;
    }
}

// ===========================================================================
// Launch sequence
// ===========================================================================
extern "C" void kernel_launch(void* const* d_in, const int* in_sizes, int n_in,
                              void* d_out, int out_size) {
    const float* x   = (const float*)d_in[0];
    const float* Wq  = (const float*)d_in[1];
    const float* bq  = (const float*)d_in[2];
    const float* Wk  = (const float*)d_in[3];
    const float* bk  = (const float*)d_in[4];
    const float* Wv  = (const float*)d_in[5];
    const float* bv  = (const float*)d_in[6];
    const float* Wfc = (const float*)d_in[7];
    const float* bfc = (const float*)d_in[8];
    const float* g1  = (const float*)d_in[9];
    const float* b1  = (const float*)d_in[10];
    const float* g2  = (const float*)d_in[11];
    const float* b2  = (const float*)d_in[12];
    float* out = (float*)d_out;

    __nv_bfloat16 *hHi, *hLo, *qkHi, *qkLo, *vtHi, *vtLo, *pHi, *pLo, *onHi, *onLo, *wtHi, *wtLo;
    float *vF, *sF, *oF;
    cudaGetSymbolAddress((void**)&hHi, g_h_hi);   cudaGetSymbolAddress((void**)&hLo, g_h_lo);
    cudaGetSymbolAddress((void**)&qkHi, g_qk_hi); cudaGetSymbolAddress((void**)&qkLo, g_qk_lo);
    cudaGetSymbolAddress((void**)&vF, g_v);
    cudaGetSymbolAddress((void**)&vtHi, g_vt_hi); cudaGetSymbolAddress((void**)&vtLo, g_vt_lo);
    cudaGetSymbolAddress((void**)&sF, g_s);
    cudaGetSymbolAddress((void**)&pHi, g_p_hi);   cudaGetSymbolAddress((void**)&pLo, g_p_lo);
    cudaGetSymbolAddress((void**)&oF, g_o);
    cudaGetSymbolAddress((void**)&onHi, g_on_hi); cudaGetSymbolAddress((void**)&onLo, g_on_lo);
    cudaGetSymbolAddress((void**)&wtHi, g_wt_hi); cudaGetSymbolAddress((void**)&wtLo, g_wt_lo);

    cudaFuncSetAttribute(hgemm3<0>, cudaFuncAttributeMaxDynamicSharedMemorySize, GEMM_SMEM);
    cudaFuncSetAttribute(hgemm3<1>, cudaFuncAttributeMaxDynamicSharedMemorySize, GEMM_SMEM);
    cudaFuncSetAttribute(hgemm3<3>, cudaFuncAttributeMaxDynamicSharedMemorySize, GEMM_SMEM);

    const long EE2 = (long)EE * EE;
    dim3 tb(32, 8);

    // 0) weight transposes + splits: wt[i][n][k] = W_i[k][n]
    transpose_split<<<dim3(32, 32, 1), tb>>>(Wq,  wtHi + 0 * EE2, wtLo + 0 * EE2, EE, EE, 0, 0);
    transpose_split<<<dim3(32, 32, 1), tb>>>(Wk,  wtHi + 1 * EE2, wtLo + 1 * EE2, EE, EE, 0, 0);
    transpose_split<<<dim3(32, 32, 1), tb>>>(Wv,  wtHi + 2 * EE2, wtLo + 2 * EE2, EE, EE, 0, 0);
    transpose_split<<<dim3(32, 32, 1), tb>>>(Wfc, wtHi + 3 * EE2, wtLo + 3 * EE2, EE, EE, 0, 0);

    // 1) h = LN(x) -> splits
    ln_split<<<NROWS, 256>>>(x, g1, b1, hHi, hLo);

    // 2) fused QKV: z in {0:q split, 1:k split, 2:v f32}
    hgemm3<0><<<dim3(EE / 128, NROWS / 128, 3), 256, GEMM_SMEM>>>(
        hHi, hLo, wtHi, wtLo, EE, EE, 0, EE2, 0,
        vF, qkHi, qkLo, bq, bk, bv, nullptr);

    // 3) v transpose+split: [B][S][EI] -> [B][EI][S]
    transpose_split<<<dim3(EE / 32, SS / 32, BB), tb>>>(
        vF, vtHi, vtLo, SS, EE, (long)SS * EE, (long)EE * SS);

    // 4) scores = q @ k^T per batch (f32 out)
    hgemm3<1><<<dim3(SS / 128, SS / 128, BB), 256, GEMM_SMEM>>>(
        qkHi, qkLo, qkHi + (long)NROWS * EE, qkLo + (long)NROWS * EE,
        EE, SS, (long)SS * EE, (long)SS * EE, (long)SS * SS,
        sF, nullptr, nullptr, nullptr, nullptr, nullptr, nullptr);

    // 5) softmax + split
    softmax_split<<<BB * SS, 256>>>(sF, pHi, pLo);

    // 6) o = attn @ v per batch (B = vt[EI][S])
    hgemm3<1><<<dim3(EE / 128, SS / 128, BB), 256, GEMM_SMEM>>>(
        pHi, pLo, vtHi, vtLo,
        SS, EE, (long)SS * SS, (long)EE * SS, (long)SS * EE,
        oF, nullptr, nullptr, nullptr, nullptr, nullptr, nullptr);

    // 7) LN2 -> splits
    ln_split<<<NROWS, 256>>>(oF, g2, b2, onHi, onLo);

    // 8) out = 2*(oln @ Wfc + bfc + x)
    hgemm3<3><<<dim3(EE / 128, NROWS / 128, 1), 256, GEMM_SMEM>>>(
        onHi, onLo, wtHi + 3 * EE2, wtLo + 3 * EE2,
        EE, EE, 0, 0, 0,
        out, nullptr, nullptr, bfc, nullptr, nullptr, x);
}